// round 2
// baseline (speedup 1.0000x reference)
#include <cuda_runtime.h>
#include <stdint.h>

// Problem constants: images [64, 3, 512, 512] fp32, PATCH=8, TOP_K=512
#define BATCH   64
#define CH      3
#define HH      512
#define WW      512
#define NPH     64          // H/PATCH
#define NPW     64          // W/PATCH
#define PP      4096        // patches per image
#define TOPK    512
#define NPATCH  (BATCH * PP)   // 262144

// Scratch (no allocations allowed in kernel_launch)
__device__ unsigned int  g_bits[NPATCH];   // contrast as orderable uint bits
__device__ unsigned char g_mask[NPATCH];   // 1 = selected

// ---------------------------------------------------------------------------
// Kernel 1: per-patch min/max -> contrast bits. One thread per patch.
// Each thread: 3 ch x 8 rows x 2 float4 loads (32B-aligned chunks).
// ---------------------------------------------------------------------------
__global__ void __launch_bounds__(256) contrast_kernel(const float* __restrict__ in) {
    int idx  = blockIdx.x * 256 + threadIdx.x;      // patch id in [0, NPATCH)
    int b    = idx >> 12;
    int pidx = idx & 4095;
    int ph   = pidx >> 6;
    int pw   = pidx & 63;

    const float4* in4 = reinterpret_cast<const float4*>(in);
    float mx = -1e30f, mn = 1e30f;

    #pragma unroll
    for (int c = 0; c < CH; c++) {
        #pragma unroll
        for (int py = 0; py < 8; py++) {
            int base = ((b * CH + c) * HH + ph * 8 + py) * (WW / 4) + pw * 2;
            float4 v0 = in4[base];
            float4 v1 = in4[base + 1];
            mx = fmaxf(mx, fmaxf(fmaxf(v0.x, v0.y), fmaxf(v0.z, v0.w)));
            mx = fmaxf(mx, fmaxf(fmaxf(v1.x, v1.y), fmaxf(v1.z, v1.w)));
            mn = fminf(mn, fminf(fminf(v0.x, v0.y), fminf(v0.z, v0.w)));
            mn = fminf(mn, fminf(fminf(v1.x, v1.y), fminf(v1.z, v1.w)));
        }
    }

    // Match JAX fp32 IEEE exactly: ((mx - mn) + eps) / (mx + mn), no contraction.
    float num = __fadd_rn(__fsub_rn(mx, mn), 1e-8f);
    float den = __fadd_rn(mx, mn);
    float ctr = __fdiv_rn(num, den);
    // ctr > 0 always -> positive-float bits order identically to float order.
    g_bits[idx] = __float_as_uint(ctr);
}

// ---------------------------------------------------------------------------
// Kernel 2: per-image exact top-512 via 4-pass 8-bit radix select on bits.
// One block per image. Tie-break matches jax.lax.top_k (stable sort:
// among equal values, lowest indices are taken first).
// ---------------------------------------------------------------------------
__global__ void __launch_bounds__(256) select_kernel() {
    __shared__ unsigned int sv[PP];
    __shared__ unsigned int hist[256];
    __shared__ unsigned int s_thr;
    __shared__ int s_rank;

    int b = blockIdx.x;
    int t = threadIdx.x;

    for (int i = t; i < PP; i += 256) sv[i] = g_bits[b * PP + i];
    if (t == 0) { s_thr = 0u; s_rank = TOPK; }
    __syncthreads();

    unsigned int prefmask = 0u;
    #pragma unroll
    for (int pass = 3; pass >= 0; pass--) {
        int shift = pass * 8;
        hist[t] = 0u;               // 256 threads, 256 bins
        __syncthreads();
        unsigned int thr = s_thr;
        for (int i = t; i < PP; i += 256) {
            unsigned int v = sv[i];
            if ((v & prefmask) == thr)
                atomicAdd(&hist[(v >> shift) & 255u], 1u);
        }
        __syncthreads();
        if (t == 0) {
            int rank = s_rank;      // looking for rank-th largest (1-based) in this bucket
            int cum = 0, bsel = 0;
            for (int bb = 255; bb >= 0; bb--) {
                int c = (int)hist[bb];
                if (cum + c >= rank) { bsel = bb; break; }
                cum += c;
            }
            s_thr  = thr | ((unsigned int)bsel << shift);
            s_rank = rank - cum;    // >= 1
        }
        prefmask |= (0xFFu << shift);
        __syncthreads();
    }

    unsigned int thr = s_thr;       // exact 512th-largest value bits
    int need = s_rank;              // how many of the == thr values to include
    for (int i = t; i < PP; i += 256) {
        unsigned int v = sv[i];
        unsigned char m = 0;
        if (v > thr) {
            m = 1;
        } else if (v == thr) {
            int eq = 0;             // equals with smaller index (ties are rare)
            for (int j = 0; j < i; j++) eq += (sv[j] == thr) ? 1 : 0;
            m = (eq < need) ? 1 : 0;
        }
        g_mask[b * PP + i] = m;
    }
}

// ---------------------------------------------------------------------------
// Kernel 3: emit output [B, P, C, 8, 8]; selected patches gather from input,
// unselected write zeros. 48 float4 per patch, 4 patches per 192-thread block.
// Output stores fully coalesced; input reads are 16B within 32B-aligned chunks.
// ---------------------------------------------------------------------------
__global__ void __launch_bounds__(192) scatter_kernel(const float* __restrict__ in,
                                                      float* __restrict__ out) {
    int t    = threadIdx.x;
    int lp   = t / 48;                       // 0..3 local patch
    int f4   = t - lp * 48;                  // 0..47 float4 slot within patch
    int gp   = blockIdx.x * 4 + lp;          // global patch id
    int b    = gp >> 12;
    int pidx = gp & 4095;
    int ph   = pidx >> 6;
    int pw   = pidx & 63;

    float4 v = make_float4(0.f, 0.f, 0.f, 0.f);
    if (g_mask[gp]) {
        int c   = f4 >> 4;                   // 0..2
        int rem = f4 & 15;
        int py  = rem >> 1;                  // 0..7
        int q   = rem & 1;                   // half-row (4 floats)
        const float4* in4 = reinterpret_cast<const float4*>(in);
        v = in4[((b * CH + c) * HH + ph * 8 + py) * (WW / 4) + pw * 2 + q];
    }
    reinterpret_cast<float4*>(out)[(size_t)gp * 48 + f4] = v;
}

// ---------------------------------------------------------------------------
extern "C" void kernel_launch(void* const* d_in, const int* in_sizes, int n_in,
                              void* d_out, int out_size) {
    const float* in  = (const float*)d_in[0];
    float*       out = (float*)d_out;

    contrast_kernel<<<NPATCH / 256, 256>>>(in);
    select_kernel<<<BATCH, 256>>>();
    scatter_kernel<<<NPATCH / 4, 192>>>(in, out);
}

// round 3
// speedup vs baseline: 1.0477x; 1.0477x over previous
#include <cuda_runtime.h>
#include <stdint.h>

// Problem constants: images [64, 3, 512, 512] fp32, PATCH=8, TOP_K=512
#define BATCH   64
#define CH      3
#define HH      512
#define WW      512
#define PP      4096        // patches per image (64x64)
#define TOPK    512
#define NPATCH  (BATCH * PP)   // 262144

// Scratch (no allocations allowed in kernel_launch)
__device__ unsigned int  g_bits[NPATCH];   // contrast as orderable uint bits
__device__ unsigned char g_mask[NPATCH];   // 1 = selected

// ---------------------------------------------------------------------------
// Kernel 1: per-patch min/max -> contrast bits. One thread per patch.
// ---------------------------------------------------------------------------
__global__ void __launch_bounds__(256) contrast_kernel(const float* __restrict__ in) {
    int idx  = blockIdx.x * 256 + threadIdx.x;      // patch id in [0, NPATCH)
    int b    = idx >> 12;
    int pidx = idx & 4095;
    int ph   = pidx >> 6;
    int pw   = pidx & 63;

    const float4* in4 = reinterpret_cast<const float4*>(in);
    float mx = -1e30f, mn = 1e30f;

    #pragma unroll
    for (int c = 0; c < CH; c++) {
        #pragma unroll
        for (int py = 0; py < 8; py++) {
            int base = ((b * CH + c) * HH + ph * 8 + py) * (WW / 4) + pw * 2;
            float4 v0 = in4[base];
            float4 v1 = in4[base + 1];
            mx = fmaxf(mx, fmaxf(fmaxf(v0.x, v0.y), fmaxf(v0.z, v0.w)));
            mx = fmaxf(mx, fmaxf(fmaxf(v1.x, v1.y), fmaxf(v1.z, v1.w)));
            mn = fminf(mn, fminf(fminf(v0.x, v0.y), fminf(v0.z, v0.w)));
            mn = fminf(mn, fminf(fminf(v1.x, v1.y), fminf(v1.z, v1.w)));
        }
    }

    // Match JAX fp32 IEEE exactly: ((mx - mn) + eps) / (mx + mn), no contraction.
    float num = __fadd_rn(__fsub_rn(mx, mn), 1e-8f);
    float den = __fadd_rn(mx, mn);
    float ctr = __fdiv_rn(num, den);
    // ctr > 0 always -> positive-float bits order identically to float order.
    g_bits[idx] = __float_as_uint(ctr);
}

// ---------------------------------------------------------------------------
// Kernel 2: per-image exact top-512 via 4-pass 8-bit radix select.
// One block per image. Warp-aggregated histogram atomics (values are highly
// concentrated -> naive atomics serialize) + parallel suffix-sum bin pick.
// Tie-break matches jax.lax.top_k (stable: lowest indices first).
// ---------------------------------------------------------------------------
__global__ void __launch_bounds__(256) select_kernel() {
    __shared__ unsigned int sv[PP];
    __shared__ unsigned int hist[256];
    __shared__ unsigned int sufs[256 + 1];
    __shared__ unsigned int s_thr;
    __shared__ int s_rank;

    int b = blockIdx.x;
    int t = threadIdx.x;
    int lane = t & 31;

    // Vectorized load of this image's 4096 contrast bits into smem.
    {
        const uint4* src = reinterpret_cast<const uint4*>(&g_bits[b * PP]);
        uint4* dst = reinterpret_cast<uint4*>(sv);
        #pragma unroll
        for (int i = 0; i < PP / 4 / 256; i++)
            dst[t + i * 256] = src[t + i * 256];
    }
    if (t == 0) { s_thr = 0u; s_rank = TOPK; }
    if (t == 0) sufs[256] = 0u;
    __syncthreads();

    unsigned int prefmask = 0u;
    #pragma unroll
    for (int pass = 3; pass >= 0; pass--) {
        int shift = pass * 8;
        hist[t] = 0u;
        __syncthreads();
        unsigned int thr = s_thr;
        int rank = s_rank;

        // Warp-aggregated histogram: threads sharing a bin combine into one atomic.
        #pragma unroll
        for (int i = 0; i < PP / 256; i++) {
            unsigned int v = sv[t + i * 256];
            bool act = ((v & prefmask) == thr);
            unsigned int actmask = __ballot_sync(0xFFFFFFFFu, act);
            if (act) {
                unsigned int bin = (v >> shift) & 255u;
                unsigned int peers = __match_any_sync(actmask, bin);
                if (lane == (__ffs(peers) - 1))
                    atomicAdd(&hist[bin], __popc(peers));
            }
        }
        __syncthreads();

        // Parallel suffix sum over 256 bins: sufs[t] = hist[t] + ... + hist[255].
        sufs[t] = hist[t];
        __syncthreads();
        #pragma unroll
        for (int off = 1; off < 256; off <<= 1) {
            unsigned int add = (t + off < 256) ? sufs[t + off] : 0u;
            __syncthreads();
            sufs[t] += add;
            __syncthreads();
        }

        // Exactly one thread's bin straddles the rank boundary.
        unsigned int above = sufs[t + 1];           // count strictly above bin t
        if (sufs[t] >= (unsigned)rank && above < (unsigned)rank) {
            s_thr  = thr | ((unsigned int)t << shift);
            s_rank = rank - (int)above;             // >= 1
        }
        prefmask |= (0xFFu << shift);
        __syncthreads();
    }

    unsigned int thr = s_thr;       // exact 512th-largest value bits
    int need = s_rank;              // how many of the == thr values to include
    #pragma unroll
    for (int ii = 0; ii < PP / 256; ii++) {
        int i = t + ii * 256;
        unsigned int v = sv[i];
        unsigned char m = 0;
        if (v > thr) {
            m = 1;
        } else if (v == thr) {
            int eq = 0;             // equals with smaller index (ties are rare)
            for (int j = 0; j < i; j++) eq += (sv[j] == thr) ? 1 : 0;
            m = (eq < need) ? 1 : 0;
        }
        g_mask[b * PP + i] = m;
    }
}

// ---------------------------------------------------------------------------
// Kernel 3: emit output [B, P, C, 8, 8]; selected patches gather from input,
// unselected write zeros. 48 float4 per patch, 8 patches per 384-thread block.
// Output stores fully coalesced float4.
// ---------------------------------------------------------------------------
__global__ void __launch_bounds__(384) scatter_kernel(const float* __restrict__ in,
                                                      float* __restrict__ out) {
    int t    = threadIdx.x;
    int lp   = t / 48;                       // 0..7 local patch
    int f4   = t - lp * 48;                  // 0..47 float4 slot within patch
    int gp   = blockIdx.x * 8 + lp;          // global patch id
    int b    = gp >> 12;
    int pidx = gp & 4095;
    int ph   = pidx >> 6;
    int pw   = pidx & 63;

    float4 v = make_float4(0.f, 0.f, 0.f, 0.f);
    if (g_mask[gp]) {
        int c   = f4 >> 4;                   // 0..2
        int rem = f4 & 15;
        int py  = rem >> 1;                  // 0..7
        int q   = rem & 1;                   // half-row (4 floats)
        const float4* in4 = reinterpret_cast<const float4*>(in);
        v = in4[((b * CH + c) * HH + ph * 8 + py) * (WW / 4) + pw * 2 + q];
    }
    reinterpret_cast<float4*>(out)[(size_t)gp * 48 + f4] = v;
}

// ---------------------------------------------------------------------------
extern "C" void kernel_launch(void* const* d_in, const int* in_sizes, int n_in,
                              void* d_out, int out_size) {
    const float* in  = (const float*)d_in[0];
    float*       out = (float*)d_out;

    contrast_kernel<<<NPATCH / 256, 256>>>(in);
    select_kernel<<<BATCH, 256>>>();
    scatter_kernel<<<NPATCH / 8, 384>>>(in, out);
}

// round 4
// speedup vs baseline: 1.3058x; 1.2464x over previous
#include <cuda_runtime.h>
#include <stdint.h>

// Problem constants: images [64, 3, 512, 512] fp32, PATCH=8, TOP_K=512
#define BATCH   64
#define CH      3
#define HH      512
#define WW      512
#define PP      4096        // patches per image (64x64)
#define TOPK    512
#define NPATCH  (BATCH * PP)   // 262144

// Scratch (no allocations allowed in kernel_launch)
__device__ unsigned int  g_bits[NPATCH];   // contrast as orderable uint bits
__device__ unsigned char g_mask[NPATCH];   // 1 = selected

// ---------------------------------------------------------------------------
// Kernel 1: per-patch min/max -> contrast bits. One thread per patch.
// ---------------------------------------------------------------------------
__global__ void __launch_bounds__(256) contrast_kernel(const float* __restrict__ in) {
    int idx  = blockIdx.x * 256 + threadIdx.x;      // patch id in [0, NPATCH)
    int b    = idx >> 12;
    int pidx = idx & 4095;
    int ph   = pidx >> 6;
    int pw   = pidx & 63;

    const float4* in4 = reinterpret_cast<const float4*>(in);
    float mx = -1e30f, mn = 1e30f;

    #pragma unroll
    for (int c = 0; c < CH; c++) {
        #pragma unroll
        for (int py = 0; py < 8; py++) {
            int base = ((b * CH + c) * HH + ph * 8 + py) * (WW / 4) + pw * 2;
            float4 v0 = in4[base];
            float4 v1 = in4[base + 1];
            mx = fmaxf(mx, fmaxf(fmaxf(v0.x, v0.y), fmaxf(v0.z, v0.w)));
            mx = fmaxf(mx, fmaxf(fmaxf(v1.x, v1.y), fmaxf(v1.z, v1.w)));
            mn = fminf(mn, fminf(fminf(v0.x, v0.y), fminf(v0.z, v0.w)));
            mn = fminf(mn, fminf(fminf(v1.x, v1.y), fminf(v1.z, v1.w)));
        }
    }

    // Match JAX fp32 IEEE exactly: ((mx - mn) + eps) / (mx + mn), no contraction.
    float num = __fadd_rn(__fsub_rn(mx, mn), 1e-8f);
    float den = __fadd_rn(mx, mn);
    float ctr = __fdiv_rn(num, den);
    // ctr > 0 always -> positive-float bits order identically to float order.
    g_bits[idx] = __float_as_uint(ctr);
}

// ---------------------------------------------------------------------------
// Kernel 2: per-image exact top-512 via 4-pass 8-bit radix select.
// One block per image. Warp-aggregated histogram atomics, parallel suffix-sum
// bin pick, and PARALLEL stable tie resolution (block scan) instead of the
// former O(P) serial loop. Tie-break matches jax.lax.top_k (lowest index).
// ---------------------------------------------------------------------------
__global__ void __launch_bounds__(256) select_kernel() {
    __shared__ unsigned int sv[PP];
    __shared__ unsigned int hist[256];
    __shared__ unsigned int sufs[256 + 1];
    __shared__ unsigned int s_thr;
    __shared__ int s_rank;
    __shared__ int wsum[8];          // per-warp equal counts
    __shared__ int wexc[8];          // exclusive warp offsets

    int b = blockIdx.x;
    int t = threadIdx.x;
    int lane = t & 31;
    int warp = t >> 5;

    // Vectorized coalesced load of this image's 4096 contrast bits into smem.
    {
        const uint4* src = reinterpret_cast<const uint4*>(&g_bits[b * PP]);
        uint4* dst = reinterpret_cast<uint4*>(sv);
        #pragma unroll
        for (int i = 0; i < PP / 4 / 256; i++)
            dst[t + i * 256] = src[t + i * 256];
    }
    if (t == 0) { s_thr = 0u; s_rank = TOPK; sufs[256] = 0u; }
    __syncthreads();

    unsigned int prefmask = 0u;
    #pragma unroll
    for (int pass = 3; pass >= 0; pass--) {
        int shift = pass * 8;
        hist[t] = 0u;
        __syncthreads();
        unsigned int thr = s_thr;
        int rank = s_rank;

        // Warp-aggregated histogram (strided, conflict-free smem reads).
        #pragma unroll
        for (int i = 0; i < PP / 256; i++) {
            unsigned int v = sv[t + i * 256];
            bool act = ((v & prefmask) == thr);
            unsigned int actmask = __ballot_sync(0xFFFFFFFFu, act);
            if (act) {
                unsigned int bin = (v >> shift) & 255u;
                unsigned int peers = __match_any_sync(actmask, bin);
                if (lane == (__ffs(peers) - 1))
                    atomicAdd(&hist[bin], __popc(peers));
            }
        }
        __syncthreads();

        // Parallel suffix sum over 256 bins: sufs[t] = hist[t..255].
        sufs[t] = hist[t];
        __syncthreads();
        #pragma unroll
        for (int off = 1; off < 256; off <<= 1) {
            unsigned int add = (t + off < 256) ? sufs[t + off] : 0u;
            __syncthreads();
            sufs[t] += add;
            __syncthreads();
        }

        // Exactly one thread's bin straddles the rank boundary.
        unsigned int above = sufs[t + 1];           // count strictly above bin t
        if (sufs[t] >= (unsigned)rank && above < (unsigned)rank) {
            s_thr  = thr | ((unsigned int)t << shift);
            s_rank = rank - (int)above;             // >= 1
        }
        prefmask |= (0xFFu << shift);
        __syncthreads();
    }

    unsigned int thr = s_thr;       // exact 512th-largest value bits
    int need = s_rank;              // how many of the == thr values to include

    // Parallel stable tie resolution: each thread owns contiguous chunk of 16.
    int base = t * 16;
    int local_eq = 0;
    #pragma unroll
    for (int k = 0; k < 16; k++)
        local_eq += (sv[base + k] == thr) ? 1 : 0;

    // Warp inclusive scan of local_eq.
    int incl = local_eq;
    #pragma unroll
    for (int off = 1; off < 32; off <<= 1) {
        int n = __shfl_up_sync(0xFFFFFFFFu, incl, off);
        if (lane >= off) incl += n;
    }
    if (lane == 31) wsum[warp] = incl;
    __syncthreads();
    if (t == 0) {
        int acc = 0;
        #pragma unroll
        for (int w = 0; w < 8; w++) { wexc[w] = acc; acc += wsum[w]; }
    }
    __syncthreads();
    int run = wexc[warp] + (incl - local_eq);   // equals with smaller index

    // Build 16 mask bytes and store as one uint4.
    union { unsigned char c[16]; uint4 v; } mb;
    #pragma unroll
    for (int k = 0; k < 16; k++) {
        unsigned int v = sv[base + k];
        unsigned char m = 0;
        if (v > thr) m = 1;
        else if (v == thr) { m = (run < need) ? 1 : 0; run++; }
        mb.c[k] = m;
    }
    reinterpret_cast<uint4*>(&g_mask[b * PP])[t] = mb.v;
}

// ---------------------------------------------------------------------------
// Kernel 3: emit output [B, P, C, 8, 8]; selected patches gather from input,
// unselected write zeros. 48 float4 per patch, 8 patches per 384-thread block.
// Output stores fully coalesced, streaming-hinted (write-once).
// ---------------------------------------------------------------------------
__global__ void __launch_bounds__(384) scatter_kernel(const float* __restrict__ in,
                                                      float* __restrict__ out) {
    int t    = threadIdx.x;
    int lp   = t / 48;                       // 0..7 local patch
    int f4   = t - lp * 48;                  // 0..47 float4 slot within patch
    int gp   = blockIdx.x * 8 + lp;          // global patch id
    int b    = gp >> 12;
    int pidx = gp & 4095;
    int ph   = pidx >> 6;
    int pw   = pidx & 63;

    float4 v = make_float4(0.f, 0.f, 0.f, 0.f);
    if (g_mask[gp]) {
        int c   = f4 >> 4;                   // 0..2
        int rem = f4 & 15;
        int py  = rem >> 1;                  // 0..7
        int q   = rem & 1;                   // half-row (4 floats)
        const float4* in4 = reinterpret_cast<const float4*>(in);
        v = in4[((b * CH + c) * HH + ph * 8 + py) * (WW / 4) + pw * 2 + q];
    }
    __stcs(&reinterpret_cast<float4*>(out)[(size_t)gp * 48 + f4], v);
}

// ---------------------------------------------------------------------------
extern "C" void kernel_launch(void* const* d_in, const int* in_sizes, int n_in,
                              void* d_out, int out_size) {
    const float* in  = (const float*)d_in[0];
    float*       out = (float*)d_out;

    contrast_kernel<<<NPATCH / 256, 256>>>(in);
    select_kernel<<<BATCH, 256>>>();
    scatter_kernel<<<NPATCH / 8, 384>>>(in, out);
}

// round 5
// speedup vs baseline: 1.3258x; 1.0153x over previous
#include <cuda_runtime.h>
#include <stdint.h>

// Problem constants: images [64, 3, 512, 512] fp32, PATCH=8, TOP_K=512
#define BATCH   64
#define CH      3
#define HH      512
#define WW      512
#define PP      4096        // patches per image (64x64)
#define TOPK    512
#define NPATCH  (BATCH * PP)   // 262144

// Scratch (no allocations allowed in kernel_launch)
__device__ unsigned int g_bits[NPATCH];          // contrast as orderable uint bits
__device__ int          g_list[BATCH * TOPK];    // selected patch idx per image

// ---------------------------------------------------------------------------
// Kernel 1: per-patch min/max -> contrast bits, FUSED with coalesced
// zero-fill of the whole output (the copy kernel later overwrites the
// selected 1/8). One thread per patch for contrast; decoupled contiguous
// indexing for the zero stores.
// ---------------------------------------------------------------------------
__global__ void __launch_bounds__(256) contrast_zero_kernel(const float* __restrict__ in,
                                                            float* __restrict__ out) {
    int t    = threadIdx.x;
    int idx  = blockIdx.x * 256 + t;                // patch id in [0, NPATCH)
    int b    = idx >> 12;
    int pidx = idx & 4095;
    int ph   = pidx >> 6;
    int pw   = pidx & 63;

    const float4* in4 = reinterpret_cast<const float4*>(in);
    float mx = -1e30f, mn = 1e30f;

    #pragma unroll
    for (int c = 0; c < CH; c++) {
        #pragma unroll
        for (int py = 0; py < 8; py++) {
            int base = ((b * CH + c) * HH + ph * 8 + py) * (WW / 4) + pw * 2;
            float4 v0 = in4[base];
            float4 v1 = in4[base + 1];
            mx = fmaxf(mx, fmaxf(fmaxf(v0.x, v0.y), fmaxf(v0.z, v0.w)));
            mx = fmaxf(mx, fmaxf(fmaxf(v1.x, v1.y), fmaxf(v1.z, v1.w)));
            mn = fminf(mn, fminf(fminf(v0.x, v0.y), fminf(v0.z, v0.w)));
            mn = fminf(mn, fminf(fminf(v1.x, v1.y), fminf(v1.z, v1.w)));
        }
    }

    // Match JAX fp32 IEEE exactly: ((mx - mn) + eps) / (mx + mn), no contraction.
    float num = __fadd_rn(__fsub_rn(mx, mn), 1e-8f);
    float den = __fadd_rn(mx, mn);
    float ctr = __fdiv_rn(num, den);
    // ctr > 0 always -> positive-float bits order identically to float order.
    g_bits[idx] = __float_as_uint(ctr);

    // Coalesced zero-fill: this block covers its 256 patches' output region
    // (256 * 48 float4 = 192 KB, contiguous).
    float4* out4 = reinterpret_cast<float4*>(out);
    size_t zbase = (size_t)blockIdx.x * 256 * 48;
    const float4 z = make_float4(0.f, 0.f, 0.f, 0.f);
    #pragma unroll
    for (int i = 0; i < 48; i++)
        __stcs(&out4[zbase + (size_t)i * 256 + t], z);
}

// ---------------------------------------------------------------------------
// Kernel 2: per-image exact top-512 via 4-pass 8-bit radix select, then
// compact the selected patch indices into g_list with a block scan (no
// atomics). Tie-break matches jax.lax.top_k (lowest index first).
// ---------------------------------------------------------------------------
__global__ void __launch_bounds__(256) select_kernel() {
    __shared__ unsigned int sv[PP];
    __shared__ unsigned int hist[256];
    __shared__ unsigned int sufs[256 + 1];
    __shared__ unsigned int s_thr;
    __shared__ int s_rank;
    __shared__ int wsum[8];
    __shared__ int wexc[8];

    int b = blockIdx.x;
    int t = threadIdx.x;
    int lane = t & 31;
    int warp = t >> 5;

    // Vectorized coalesced load of this image's 4096 contrast bits into smem.
    {
        const uint4* src = reinterpret_cast<const uint4*>(&g_bits[b * PP]);
        uint4* dst = reinterpret_cast<uint4*>(sv);
        #pragma unroll
        for (int i = 0; i < PP / 4 / 256; i++)
            dst[t + i * 256] = src[t + i * 256];
    }
    if (t == 0) { s_thr = 0u; s_rank = TOPK; sufs[256] = 0u; }
    __syncthreads();

    unsigned int prefmask = 0u;
    #pragma unroll
    for (int pass = 3; pass >= 0; pass--) {
        int shift = pass * 8;
        hist[t] = 0u;
        __syncthreads();
        unsigned int thr = s_thr;
        int rank = s_rank;

        // Warp-aggregated histogram (values are highly concentrated).
        #pragma unroll
        for (int i = 0; i < PP / 256; i++) {
            unsigned int v = sv[t + i * 256];
            bool act = ((v & prefmask) == thr);
            unsigned int actmask = __ballot_sync(0xFFFFFFFFu, act);
            if (act) {
                unsigned int bin = (v >> shift) & 255u;
                unsigned int peers = __match_any_sync(actmask, bin);
                if (lane == (__ffs(peers) - 1))
                    atomicAdd(&hist[bin], __popc(peers));
            }
        }
        __syncthreads();

        // Parallel suffix sum over 256 bins: sufs[t] = hist[t..255].
        sufs[t] = hist[t];
        __syncthreads();
        #pragma unroll
        for (int off = 1; off < 256; off <<= 1) {
            unsigned int add = (t + off < 256) ? sufs[t + off] : 0u;
            __syncthreads();
            sufs[t] += add;
            __syncthreads();
        }

        // Exactly one thread's bin straddles the rank boundary.
        unsigned int above = sufs[t + 1];
        if (sufs[t] >= (unsigned)rank && above < (unsigned)rank) {
            s_thr  = thr | ((unsigned int)t << shift);
            s_rank = rank - (int)above;             // >= 1
        }
        prefmask |= (0xFFu << shift);
        __syncthreads();
    }

    unsigned int thr = s_thr;       // exact 512th-largest value bits
    int need = s_rank;              // how many of the == thr values to include

    // Each thread owns a contiguous chunk of 16 patches.
    int base = t * 16;

    // ---- stable tie resolution: scan of equal-to-threshold counts ----
    int local_eq = 0;
    #pragma unroll
    for (int k = 0; k < 16; k++)
        local_eq += (sv[base + k] == thr) ? 1 : 0;

    int incl = local_eq;
    #pragma unroll
    for (int off = 1; off < 32; off <<= 1) {
        int n = __shfl_up_sync(0xFFFFFFFFu, incl, off);
        if (lane >= off) incl += n;
    }
    if (lane == 31) wsum[warp] = incl;
    __syncthreads();
    if (t == 0) {
        int acc = 0;
        #pragma unroll
        for (int w = 0; w < 8; w++) { wexc[w] = acc; acc += wsum[w]; }
    }
    __syncthreads();
    int run = wexc[warp] + (incl - local_eq);   // equals with smaller index

    // ---- build selection bits for my 16 patches ----
    unsigned int selbits = 0u;
    #pragma unroll
    for (int k = 0; k < 16; k++) {
        unsigned int v = sv[base + k];
        bool m = false;
        if (v > thr) m = true;
        else if (v == thr) { m = (run < need); run++; }
        selbits |= (m ? 1u : 0u) << k;
    }
    __syncthreads();

    // ---- compact selected indices via a second block scan ----
    int local_sel = __popc(selbits);
    int incl2 = local_sel;
    #pragma unroll
    for (int off = 1; off < 32; off <<= 1) {
        int n = __shfl_up_sync(0xFFFFFFFFu, incl2, off);
        if (lane >= off) incl2 += n;
    }
    if (lane == 31) wsum[warp] = incl2;
    __syncthreads();
    if (t == 0) {
        int acc = 0;
        #pragma unroll
        for (int w = 0; w < 8; w++) { wexc[w] = acc; acc += wsum[w]; }
    }
    __syncthreads();
    int pos = wexc[warp] + (incl2 - local_sel);

    int* lst = &g_list[b * TOPK];
    #pragma unroll
    for (int k = 0; k < 16; k++) {
        if ((selbits >> k) & 1u)
            lst[pos++] = base + k;      // patch idx within image
    }
}

// ---------------------------------------------------------------------------
// Kernel 3: copy ONLY the selected patches (dense list — exactly 512/image).
// 8 patches per 384-thread block; 48 consecutive float4 stores per patch.
// ---------------------------------------------------------------------------
__global__ void __launch_bounds__(384) copy_kernel(const float* __restrict__ in,
                                                   float* __restrict__ out) {
    int t   = threadIdx.x;
    int lp  = t / 48;                        // 0..7 local patch
    int f4  = t - lp * 48;                   // 0..47 float4 slot within patch
    int j   = blockIdx.x * 8 + lp;           // dense selected index [0, 32768)
    int b   = j >> 9;                        // image (512 per image)
    int pidx = g_list[j];                    // patch idx within image
    int gp  = b * PP + pidx;
    int ph  = pidx >> 6;
    int pw  = pidx & 63;

    int c   = f4 >> 4;                       // 0..2
    int rem = f4 & 15;
    int py  = rem >> 1;                      // 0..7
    int q   = rem & 1;                       // half-row (4 floats)

    const float4* in4 = reinterpret_cast<const float4*>(in);
    float4 v = in4[((b * CH + c) * HH + ph * 8 + py) * (WW / 4) + pw * 2 + q];
    reinterpret_cast<float4*>(out)[(size_t)gp * 48 + f4] = v;
}

// ---------------------------------------------------------------------------
extern "C" void kernel_launch(void* const* d_in, const int* in_sizes, int n_in,
                              void* d_out, int out_size) {
    const float* in  = (const float*)d_in[0];
    float*       out = (float*)d_out;

    contrast_zero_kernel<<<NPATCH / 256, 256>>>(in, out);
    select_kernel<<<BATCH, 256>>>();
    copy_kernel<<<(BATCH * TOPK) / 8, 384>>>(in, out);
}

// round 6
// speedup vs baseline: 1.4329x; 1.0808x over previous
#include <cuda_runtime.h>
#include <stdint.h>

// Problem constants: images [64, 3, 512, 512] fp32, PATCH=8, TOP_K=512
#define BATCH   64
#define CH      3
#define HH      512
#define WW      512
#define PP      4096        // patches per image (64x64)
#define TOPK    512
#define NUNSEL  (PP - TOPK)            // 3584 unselected per image (exact)
#define NPATCH  (BATCH * PP)           // 262144

#define COPY_BLOCKS  ((BATCH * TOPK) / 8)     // 4096
#define ZERO_BLOCKS  ((BATCH * NUNSEL) / 8)   // 28672

// Scratch (no allocations allowed in kernel_launch)
__device__ unsigned int g_bits[NPATCH];            // contrast as orderable uint bits
__device__ int          g_sel[BATCH * TOPK];       // selected patch idx per image
__device__ int          g_uns[BATCH * NUNSEL];     // unselected patch idx per image

// ---------------------------------------------------------------------------
// Kernel 1: per-patch min/max -> contrast bits. One thread per patch.
// Pure streaming read; 79% DRAM.
// ---------------------------------------------------------------------------
__global__ void __launch_bounds__(256) contrast_kernel(const float* __restrict__ in) {
    int idx  = blockIdx.x * 256 + threadIdx.x;      // patch id in [0, NPATCH)
    int b    = idx >> 12;
    int pidx = idx & 4095;
    int ph   = pidx >> 6;
    int pw   = pidx & 63;

    const float4* in4 = reinterpret_cast<const float4*>(in);
    float mx = -1e30f, mn = 1e30f;

    #pragma unroll
    for (int c = 0; c < CH; c++) {
        #pragma unroll
        for (int py = 0; py < 8; py++) {
            int base = ((b * CH + c) * HH + ph * 8 + py) * (WW / 4) + pw * 2;
            float4 v0 = in4[base];
            float4 v1 = in4[base + 1];
            mx = fmaxf(mx, fmaxf(fmaxf(v0.x, v0.y), fmaxf(v0.z, v0.w)));
            mx = fmaxf(mx, fmaxf(fmaxf(v1.x, v1.y), fmaxf(v1.z, v1.w)));
            mn = fminf(mn, fminf(fminf(v0.x, v0.y), fminf(v0.z, v0.w)));
            mn = fminf(mn, fminf(fminf(v1.x, v1.y), fminf(v1.z, v1.w)));
        }
    }

    // Match JAX fp32 IEEE exactly: ((mx - mn) + eps) / (mx + mn), no contraction.
    float num = __fadd_rn(__fsub_rn(mx, mn), 1e-8f);
    float den = __fadd_rn(mx, mn);
    float ctr = __fdiv_rn(num, den);
    // ctr > 0 always -> positive-float bits order identically to float order.
    g_bits[idx] = __float_as_uint(ctr);
}

// ---------------------------------------------------------------------------
// Block-scan helper state lives in shared; small utility done inline below.
// ---------------------------------------------------------------------------

// ---------------------------------------------------------------------------
// Kernel 2: per-image exact top-512 via 4-pass 8-bit radix select, then
// compact BOTH the selected (512) and unselected (3584) patch index lists
// via block scans (no atomics). Tie-break matches jax.lax.top_k.
// ---------------------------------------------------------------------------
__global__ void __launch_bounds__(256) select_kernel() {
    __shared__ unsigned int sv[PP];
    __shared__ unsigned int hist[256];
    __shared__ unsigned int sufs[256 + 1];
    __shared__ unsigned int s_thr;
    __shared__ int s_rank;
    __shared__ int wsum[8];
    __shared__ int wexc[8];

    int b = blockIdx.x;
    int t = threadIdx.x;
    int lane = t & 31;
    int warp = t >> 5;

    // Vectorized coalesced load of this image's 4096 contrast bits into smem.
    {
        const uint4* src = reinterpret_cast<const uint4*>(&g_bits[b * PP]);
        uint4* dst = reinterpret_cast<uint4*>(sv);
        #pragma unroll
        for (int i = 0; i < PP / 4 / 256; i++)
            dst[t + i * 256] = src[t + i * 256];
    }
    if (t == 0) { s_thr = 0u; s_rank = TOPK; sufs[256] = 0u; }
    __syncthreads();

    unsigned int prefmask = 0u;
    #pragma unroll
    for (int pass = 3; pass >= 0; pass--) {
        int shift = pass * 8;
        hist[t] = 0u;
        __syncthreads();
        unsigned int thr = s_thr;
        int rank = s_rank;

        // Warp-aggregated histogram (values are highly concentrated).
        #pragma unroll
        for (int i = 0; i < PP / 256; i++) {
            unsigned int v = sv[t + i * 256];
            bool act = ((v & prefmask) == thr);
            unsigned int actmask = __ballot_sync(0xFFFFFFFFu, act);
            if (act) {
                unsigned int bin = (v >> shift) & 255u;
                unsigned int peers = __match_any_sync(actmask, bin);
                if (lane == (__ffs(peers) - 1))
                    atomicAdd(&hist[bin], __popc(peers));
            }
        }
        __syncthreads();

        // Parallel suffix sum over 256 bins: sufs[t] = hist[t..255].
        sufs[t] = hist[t];
        __syncthreads();
        #pragma unroll
        for (int off = 1; off < 256; off <<= 1) {
            unsigned int add = (t + off < 256) ? sufs[t + off] : 0u;
            __syncthreads();
            sufs[t] += add;
            __syncthreads();
        }

        // Exactly one thread's bin straddles the rank boundary.
        unsigned int above = sufs[t + 1];
        if (sufs[t] >= (unsigned)rank && above < (unsigned)rank) {
            s_thr  = thr | ((unsigned int)t << shift);
            s_rank = rank - (int)above;             // >= 1
        }
        prefmask |= (0xFFu << shift);
        __syncthreads();
    }

    unsigned int thr = s_thr;       // exact 512th-largest value bits
    int need = s_rank;              // how many of the == thr values to include

    // Each thread owns a contiguous chunk of 16 patches.
    int base = t * 16;

    // ---- stable tie resolution: scan of equal-to-threshold counts ----
    int local_eq = 0;
    #pragma unroll
    for (int k = 0; k < 16; k++)
        local_eq += (sv[base + k] == thr) ? 1 : 0;

    int incl = local_eq;
    #pragma unroll
    for (int off = 1; off < 32; off <<= 1) {
        int n = __shfl_up_sync(0xFFFFFFFFu, incl, off);
        if (lane >= off) incl += n;
    }
    if (lane == 31) wsum[warp] = incl;
    __syncthreads();
    if (t == 0) {
        int acc = 0;
        #pragma unroll
        for (int w = 0; w < 8; w++) { wexc[w] = acc; acc += wsum[w]; }
    }
    __syncthreads();
    int run = wexc[warp] + (incl - local_eq);   // equals with smaller index

    // ---- build selection bits for my 16 patches ----
    unsigned int selbits = 0u;
    #pragma unroll
    for (int k = 0; k < 16; k++) {
        unsigned int v = sv[base + k];
        bool m = false;
        if (v > thr) m = true;
        else if (v == thr) { m = (run < need); run++; }
        selbits |= (m ? 1u : 0u) << k;
    }
    __syncthreads();

    // ---- compact selected indices via block scan ----
    int local_sel = __popc(selbits);
    int incl2 = local_sel;
    #pragma unroll
    for (int off = 1; off < 32; off <<= 1) {
        int n = __shfl_up_sync(0xFFFFFFFFu, incl2, off);
        if (lane >= off) incl2 += n;
    }
    if (lane == 31) wsum[warp] = incl2;
    __syncthreads();
    if (t == 0) {
        int acc = 0;
        #pragma unroll
        for (int w = 0; w < 8; w++) { wexc[w] = acc; acc += wsum[w]; }
    }
    __syncthreads();
    int pos  = wexc[warp] + (incl2 - local_sel);         // selected offset
    int upos = base - pos;                               // unselected offset
                                                         // (excl. scan of complement
                                                         //  = base - excl. selected)
    int* sl = &g_sel[b * TOPK];
    int* ul = &g_uns[b * NUNSEL];
    #pragma unroll
    for (int k = 0; k < 16; k++) {
        int pidx = base + k;
        if ((selbits >> k) & 1u) sl[pos++] = pidx;
        else                     ul[upos++] = pidx;
    }
}

// ---------------------------------------------------------------------------
// Kernel 3: single output pass. Blocks [0, COPY_BLOCKS) gather-copy the
// selected patches (launched first so the random 32B reads overlap with the
// zero stream); blocks [COPY_BLOCKS, ...) zero the unselected patches.
// 8 patches per 384-thread block, 48 float4 per patch, uniform per block.
// Every output byte written exactly once, streaming-hinted.
// ---------------------------------------------------------------------------
__global__ void __launch_bounds__(384) output_kernel(const float* __restrict__ in,
                                                     float* __restrict__ out) {
    int t   = threadIdx.x;
    int lp  = t / 48;                        // 0..7 local patch
    int f4  = t - lp * 48;                   // 0..47 float4 slot within patch
    float4* out4 = reinterpret_cast<float4*>(out);

    if (blockIdx.x < COPY_BLOCKS) {
        int j    = blockIdx.x * 8 + lp;      // dense selected index [0, 32768)
        int b    = j >> 9;                   // 512 selected per image
        int pidx = g_sel[j];
        int gp   = b * PP + pidx;
        int ph   = pidx >> 6;
        int pw   = pidx & 63;

        int c   = f4 >> 4;                   // 0..2
        int rem = f4 & 15;
        int py  = rem >> 1;                  // 0..7
        int q   = rem & 1;                   // half-row (4 floats)

        const float4* in4 = reinterpret_cast<const float4*>(in);
        float4 v = __ldcs(&in4[((b * CH + c) * HH + ph * 8 + py) * (WW / 4) + pw * 2 + q]);
        __stcs(&out4[(size_t)gp * 48 + f4], v);
    } else {
        int j    = (blockIdx.x - COPY_BLOCKS) * 8 + lp;   // dense unselected idx
        int b    = j / NUNSEL;
        int u    = j - b * NUNSEL;
        int pidx = g_uns[b * NUNSEL + u];
        int gp   = b * PP + pidx;
        const float4 z = make_float4(0.f, 0.f, 0.f, 0.f);
        __stcs(&out4[(size_t)gp * 48 + f4], z);
    }
}

// ---------------------------------------------------------------------------
extern "C" void kernel_launch(void* const* d_in, const int* in_sizes, int n_in,
                              void* d_out, int out_size) {
    const float* in  = (const float*)d_in[0];
    float*       out = (float*)d_out;

    contrast_kernel<<<NPATCH / 256, 256>>>(in);
    select_kernel<<<BATCH, 256>>>();
    output_kernel<<<COPY_BLOCKS + ZERO_BLOCKS, 384>>>(in, out);
}